// round 17
// baseline (speedup 1.0000x reference)
#include <cuda_runtime.h>

typedef unsigned u32;
typedef unsigned long long ull;

#define BB 256
#define TT 50
#define IDD 16
#define NCV 32
#define D0V 512
#define DINV 528
#define HIDV 512
#define NSTEPS 5
#define DT_C 0.05f
#define HS 1056
#define G_CTAS 136
#define NTHR 256

// smem layout (floats): W k-major stride 33 (fp32, as r8); X double-buffered
// 32-k chunks stored as tf32 hi/lo pairs: [k*33 + row] float2, 2112 floats/buf
#define WS1_OFF 0
#define WS2_OFF (544 * 33)                 // 17952
#define WS3_OFF (WS2_OFF + 512 * 33)       // 34848
#define XD_OFF  (WS3_OFF + 512 * 33)       // 51744
#define XD_BUF  (33 * 32 * 2)              // 2112 floats (1056 float2)
#define SMEM_FLOATS (XD_OFF + 2 * XD_BUF)  // 55968
#define SMEM_BYTES  (SMEM_FLOATS * 4)      // 223872 B (< 227KB opt-in)

__device__ float g_h[2][BB * HS];
__device__ float g_a0[BB * HIDV];
__device__ float g_a1[BB * HIDV];
__device__ unsigned g_cnt[8 * 32];
__device__ unsigned g_gen[8 * 32];

__device__ __forceinline__ unsigned ld_acq(const unsigned* p) {
    unsigned v; asm volatile("ld.acquire.gpu.u32 %0, [%1];" : "=r"(v) : "l"(p) : "memory"); return v;
}
__device__ __forceinline__ void st_rel(unsigned* p, unsigned v) {
    asm volatile("st.release.gpu.u32 [%0], %1;" :: "l"(p), "r"(v) : "memory");
}
__device__ __forceinline__ unsigned atom_add_acqrel(unsigned* p, unsigned v) {
    unsigned o; asm volatile("atom.add.acq_rel.gpu.u32 %0, [%1], %2;" : "=r"(o) : "l"(p), "r"(v) : "memory"); return o;
}

__device__ __forceinline__ void group_sync(int rb) {
    __syncthreads();
    if (threadIdx.x == 0) {
        const int s = rb * 32;
        unsigned gen = ld_acq(&g_gen[s]);
        if (atom_add_acqrel(&g_cnt[s], 1u) == 16u) {
            g_cnt[s] = 0u;
            st_rel(&g_gen[s], gen + 1u);
        } else {
            while (ld_acq(&g_gen[s]) == gen) { }
        }
    }
    __syncthreads();
}

// ---- tf32 helpers ----
__device__ __forceinline__ u32 to_tf32(float x) {
    u32 r; asm("cvt.rna.tf32.f32 %0, %1;" : "=r"(r) : "f"(x)); return r;
}
__device__ __forceinline__ void mma8(float* d, const u32* a, u32 b0, u32 b1) {
    asm volatile("mma.sync.aligned.m16n8k8.row.col.f32.tf32.tf32.f32 "
        "{%0,%1,%2,%3}, {%4,%5,%6,%7}, {%8,%9}, {%0,%1,%2,%3};"
        : "+f"(d[0]), "+f"(d[1]), "+f"(d[2]), "+f"(d[3])
        : "r"(a[0]), "r"(a[1]), "r"(a[2]), "r"(a[3]), "r"(b0), "r"(b1));
}

// split one float4 (4 consecutive k of one row) into tf32 hi/lo pairs in smem
__device__ __forceinline__ void xsplit_store(float2* d, float4 v, int lq, int lr) {
    #pragma unroll
    for (int m = 0; m < 4; m++) {
        const float x = (&v.x)[m];
        const u32 th = to_tf32(x);
        const float hf = __uint_as_float(th);
        const u32 tl = to_tf32(x - hf);
        d[(4 * lq + m) * 33 + lr] = make_float2(__uint_as_float(th), __uint_as_float(tl));
    }
}

// ---- tf32 tensor GEMM: 32x32 tile, 8 warps each own one m16n8 subtile ----
// MODE 0/1: outbuf[row*512+col] = relu(v + bias) ; MODE 2: hn = hc + DT*(v+bias), col<528
template <int MODE>
__device__ __forceinline__ void gemm_ks(const float* __restrict__ X, int xs, int nch,
                                        const float* __restrict__ Wsm,
                                        const float* __restrict__ bias,
                                        float* __restrict__ outbuf,
                                        const float* __restrict__ hc,
                                        float* __restrict__ hn,
                                        float* __restrict__ Xs, int r0, int c0) {
    const int tid = threadIdx.x;
    const int w = tid >> 5, l = tid & 31;
    const int wr = w >> 2, wc = w & 3;        // warp -> rows wr*16..+15, cols wc*8..+7
    const int lr = tid & 31, lq = tid >> 5;   // loader: row, k-quad (0..7)

    float dhh[4] = {0.f, 0.f, 0.f, 0.f};
    float dhl[4] = {0.f, 0.f, 0.f, 0.f};
    float dlh[4] = {0.f, 0.f, 0.f, 0.f};

    const float* xr = X + (r0 + lr) * xs;
    float4 pa = *(const float4*)(xr + 4 * lq);
    xsplit_store((float2*)Xs, pa, lq, lr);
    if (nch > 1) pa = *(const float4*)(xr + 32 + 4 * lq);
    __syncthreads();

    const int kk = l & 3;
    const int ar = wr * 16 + (l >> 2);
    const int bn = wc * 8 + (l >> 2);

    for (int ch = 0; ch < nch; ch++) {
        if (ch + 1 < nch)
            xsplit_store((float2*)(Xs + ((ch + 1) & 1) * XD_BUF), pa, lq, lr);
        if (ch + 2 < nch)
            pa = *(const float4*)(xr + (ch + 2) * 32 + 4 * lq);

        const uint2* xb = (const uint2*)(Xs + (ch & 1) * XD_BUF);
        const float* wb = Wsm + (ch * 32) * 33 + bn;
        #pragma unroll
        for (int ks = 0; ks < 4; ks++) {
            const int kb = ks * 8 + kk;
            uint2 q0 = xb[kb * 33 + ar];
            uint2 q1 = xb[kb * 33 + ar + 8];
            uint2 q2 = xb[(kb + 4) * 33 + ar];
            uint2 q3 = xb[(kb + 4) * 33 + ar + 8];
            const float wv0 = wb[kb * 33];
            const float wv1 = wb[(kb + 4) * 33];
            const u32 bh0 = to_tf32(wv0);
            const u32 bl0 = to_tf32(wv0 - __uint_as_float(bh0));
            const u32 bh1 = to_tf32(wv1);
            const u32 bl1 = to_tf32(wv1 - __uint_as_float(bh1));
            u32 ah[4] = {q0.x, q1.x, q2.x, q3.x};
            u32 al[4] = {q0.y, q1.y, q2.y, q3.y};
            mma8(dhh, ah, bh0, bh1);
            mma8(dhl, ah, bl0, bl1);
            mma8(dlh, al, bh0, bh1);
        }
        __syncthreads();
    }

    const float f0 = dhh[0] + dlh[0] + dhl[0];
    const float f1 = dhh[1] + dlh[1] + dhl[1];
    const float f2 = dhh[2] + dlh[2] + dhl[2];
    const float f3 = dhh[3] + dlh[3] + dhl[3];

    const int ra = r0 + wr * 16 + (l >> 2);
    const int cb = c0 + wc * 8 + 2 * (l & 3);
    if (MODE != 2) {
        float2 bv = *(const float2*)&bias[cb];
        *(float2*)&outbuf[ra * 512 + cb] =
            make_float2(fmaxf(f0 + bv.x, 0.f), fmaxf(f1 + bv.y, 0.f));
        *(float2*)&outbuf[(ra + 8) * 512 + cb] =
            make_float2(fmaxf(f2 + bv.x, 0.f), fmaxf(f3 + bv.y, 0.f));
    } else if (cb < DINV) {
        float2 bv = *(const float2*)&bias[cb];
        const long i0 = (long)ra * HS + 512 + cb;
        const long i2 = (long)(ra + 8) * HS + 512 + cb;
        hn[i0] = hc[i0] + DT_C * (f0 + bv.x);
        hn[i0 + 1] = hc[i0 + 1] + DT_C * (f1 + bv.y);
        hn[i2] = hc[i2] + DT_C * (f2 + bv.x);
        hn[i2 + 1] = hc[i2 + 1] + DT_C * (f3 + bv.y);
    }
}

// ---- cn0 ODE phase (j==16 CTA; A/Bv cached in its free W1 smem) ----
__device__ __forceinline__ void cnode_phase(int rb, const float* __restrict__ hc,
                                            float* __restrict__ hn,
                                            const float* __restrict__ As,
                                            const float* __restrict__ Bs) {
    const int tid = threadIdx.x;
    const int b0 = rb * 32;
    #pragma unroll
    for (int rep = 0; rep < 2; rep++) {
        const int item = rep * NTHR + tid;
        const int b = b0 + (item >> 4);
        const int i = item & 15;
        const float* hr = hc + b * HS;
        float x[32];
        const float4* cpp = (const float4*)(hr + i * 32);
        #pragma unroll
        for (int q = 0; q < 8; q++) {
            float4 v = cpp[q];
            x[4 * q] = v.x; x[4 * q + 1] = v.y; x[4 * q + 2] = v.z; x[4 * q + 3] = v.w;
        }
        const float cn1v = hr[512 + i];
        float* outp = hn + b * HS + i * 32;
        #pragma unroll 4
        for (int n = 0; n < 32; n++) {
            float acc = Bs[n] * cn1v;
            const float4* ap = (const float4*)(As + n * 32);
            #pragma unroll
            for (int q = 0; q < 8; q++) {
                float4 a4 = ap[q];
                acc = fmaf(x[4 * q], a4.x, acc);
                acc = fmaf(x[4 * q + 1], a4.y, acc);
                acc = fmaf(x[4 * q + 2], a4.z, acc);
                acc = fmaf(x[4 * q + 3], a4.w, acc);
            }
            outp[n] = x[n] + DT_C * acc;
        }
    }
}

__device__ __forceinline__ void obs_phase(int rb, int j, int t,
                                          const float* __restrict__ Y,
                                          const float* __restrict__ mask,
                                          float* __restrict__ h, float* __restrict__ out,
                                          long off_traj, long off_lasth, int tlast) {
    const int gid = j * NTHR + threadIdx.x;
    const int nth = 17 * NTHR;
    const int b0 = rb * 32;
    for (int idx = gid; idx < 32 * DINV; idx += nth) {
        const int b = b0 + idx / DINV;
        const int c = idx % DINV;
        const float m = mask[b * TT + t];
        float* hr = h + b * HS;
        const float he = hr[512 + c];
        if (c < IDD) {
            const long po = (long)(b * TT + t) * IDD + c;
            out[po] = he;
            if (off_traj >= 0) out[off_traj + po] = he;
            const float y = Y[(b * TT + t) * IDD + c];
            hr[512 + c] = m * y + (1.f - m) * he;
        } else {
            hr[512 + c] = m * hr[c - IDD] + (1.f - m) * he;
        }
    }
    if (t == tlast) {
        for (int idx = gid; idx < 32 * D0V; idx += nth) {
            const int b = b0 + (idx >> 9);
            const int jj = idx & 511;
            out[off_lasth + (long)b * D0V + jj] = h[b * HS + jj];
        }
    }
}

__global__ void __launch_bounds__(NTHR, 1)
cnode_persistent(const float* __restrict__ times,
                 const float* __restrict__ Y, const float* __restrict__ mask,
                 const float* __restrict__ A, const float* __restrict__ Bv,
                 const float* __restrict__ W1, const float* __restrict__ b1,
                 const float* __restrict__ W2, const float* __restrict__ b2,
                 const float* __restrict__ W3, const float* __restrict__ b3,
                 float* __restrict__ out,
                 long off_traj, long off_times, long off_lasth, long off_hfin) {
    extern __shared__ float sm[];
    __shared__ int s_tl;
    const int cta = blockIdx.x;
    const int tid = threadIdx.x;
    const int rb = cta / 17;
    const int j  = cta - rb * 17;
    const int r0 = rb * 32;
    const int c0 = j * 32;

    if (tid == 0) s_tl = -1;
    __syncthreads();
    {
        int local = -1;
        for (int idx = tid; idx < BB * TT; idx += NTHR)
            if (mask[idx] > 0.f) { int t = idx % TT; if (t > local) local = t; }
        if (local >= 0) atomicMax(&s_tl, local);
    }
    {
        const int gid = j * NTHR + tid;
        const int nth = 17 * NTHR;
        for (int idx = gid; idx < 32 * HS; idx += nth) {
            const int b = r0 + idx / HS, c = idx % HS;
            g_h[0][b * HS + c] = 0.f;
            g_h[1][b * HS + c] = 0.f;
        }
        for (int idx = gid; idx < 32 * D0V; idx += nth)
            out[off_lasth + (long)r0 * D0V + idx] = 0.f;
    }
    if (cta == 0 && tid < TT) out[off_times + tid] = times[tid];

    // resident weights, k-major stride 33 (fp32)
    if (j < 16) {
        for (int idx = tid; idx < 544 * 32; idx += NTHR) {
            const int k = idx >> 5, lc = idx & 31;
            sm[WS1_OFF + k * 33 + lc] = (k < DINV) ? W1[k * HIDV + c0 + lc] : 0.f;
        }
        for (int idx = tid; idx < 512 * 32; idx += NTHR) {
            const int k = idx >> 5, lc = idx & 31;
            sm[WS2_OFF + k * 33 + lc] = W2[k * HIDV + c0 + lc];
        }
    } else {
        for (int i = tid; i < NCV * NCV; i += NTHR) sm[WS1_OFF + i] = A[i];
        for (int i = tid; i < NCV; i += NTHR) sm[WS1_OFF + 1024 + i] = Bv[i];
    }
    for (int idx = tid; idx < 512 * 32; idx += NTHR) {
        const int k = idx >> 5, lc = idx & 31;
        const int c = c0 + lc;
        sm[WS3_OFF + k * 33 + lc] = (c < DINV) ? W3[k * DINV + c] : 0.f;
    }
    __syncthreads();
    const int tlast = s_tl;
    group_sync(rb);

    float* Xd = sm + XD_OFF;
    int cur = 0;
    for (int t = 0; t < TT; t++) {
        for (int s = 0; s < NSTEPS; s++) {
            float* hc = g_h[cur];
            float* hn = g_h[cur ^ 1];
            if (j < 16)
                gemm_ks<0>(hc + 512, HS, 17, sm + WS1_OFF, b1, g_a0, 0, 0, Xd, r0, c0);
            else
                cnode_phase(rb, hc, hn, sm + WS1_OFF, sm + WS1_OFF + 1024);
            group_sync(rb);
            if (j < 16)
                gemm_ks<1>(g_a0, HIDV, 16, sm + WS2_OFF, b2, g_a1, 0, 0, Xd, r0, c0);
            group_sync(rb);
            gemm_ks<2>(g_a1, HIDV, 16, sm + WS3_OFF, b3, 0, hc, hn, Xd, r0, c0);
            group_sync(rb);
            cur ^= 1;
        }
        obs_phase(rb, j, t, Y, mask, g_h[cur], out, off_traj, off_lasth, tlast);
        group_sync(rb);
    }
    const int gid = j * NTHR + tid;
    const float* h = g_h[cur];
    for (int idx = gid; idx < 32 * 1040; idx += 17 * NTHR) {
        const int b = r0 + idx / 1040, c = idx % 1040;
        out[off_hfin + (long)b * 1040 + c] = h[b * HS + c];
    }
}

extern "C" void kernel_launch(void* const* d_in, const int* in_sizes, int n_in,
                              void* d_out, int out_size) {
    const float* times = (const float*)d_in[0];
    const float* Y     = (const float*)d_in[1];
    const float* mask  = (const float*)d_in[2];
    const float* A     = (const float*)d_in[3];
    const float* Bv    = (const float*)d_in[4];
    const float* W1    = (const float*)d_in[5];
    const float* b1    = (const float*)d_in[6];
    const float* W2    = (const float*)d_in[7];
    const float* b2    = (const float*)d_in[8];
    const float* W3    = (const float*)d_in[9];
    const float* b3    = (const float*)d_in[10];
    float* out = (float*)d_out;

    cudaFuncSetAttribute(cnode_persistent,
                         cudaFuncAttributeMaxDynamicSharedMemorySize, SMEM_BYTES);

    const long np = (long)BB * TT * IDD;
    long off_traj, off_times, off_lasth, off_hfin;
    const long full = 2 * np + TT + (long)BB * D0V + (long)BB * (2 * D0V + IDD);
    if ((long)out_size >= full) { off_traj = np; off_times = 2 * np; }
    else { off_traj = -1; off_times = np; }
    off_lasth = off_times + TT;
    off_hfin = off_lasth + (long)BB * D0V;

    cnode_persistent<<<G_CTAS, NTHR, SMEM_BYTES>>>(times, Y, mask, A, Bv,
                                                   W1, b1, W2, b2, W3, b3,
                                                   out, off_traj, off_times,
                                                   off_lasth, off_hfin);
}